// round 16
// baseline (speedup 1.0000x reference)
#include <cuda_runtime.h>
#include <cuda_fp16.h>
#include <cuda_bf16.h>
#include <cstdint>

#define N_NODES 100000
#define N_EDGES 1600000
#define D 128

#define SCAN_B 512
#define NUM_SCAN_BLOCKS ((N_NODES + SCAN_B - 1) / SCAN_B)   // 196

// Scratch (device globals: allocation-free, zero-initialized at module load).
// g_deg_s / g_deg_r are re-zeroed by gather_kernel each call.
__device__ __half g_h[(size_t)N_NODES * D];   // 25.6 MB, fp16 h = (xW+b)*rsqrt(deg_s)
__device__ int    g_deg_s[N_NODES];
__device__ int    g_deg_r[N_NODES];
__device__ int    g_off[N_NODES];             // after fill: END offset per node
__device__ int    g_bsum[NUM_SCAN_BLOCKS];
__device__ int    g_csr[N_EDGES];

// ---------------------------------------------------------------------------
// degree: int4-vectorized (4 edges per thread; N_EDGES % 4 == 0)
// ---------------------------------------------------------------------------
__global__ void degree_kernel(const int* __restrict__ s, const int* __restrict__ r)
{
    const int i = blockIdx.x * blockDim.x + threadIdx.x;
    if (i < N_EDGES / 4) {
        const int4 a = reinterpret_cast<const int4*>(s)[i];
        atomicAdd(&g_deg_s[a.x], 1);
        atomicAdd(&g_deg_s[a.y], 1);
        atomicAdd(&g_deg_s[a.z], 1);
        atomicAdd(&g_deg_s[a.w], 1);
        const int4 b = reinterpret_cast<const int4*>(r)[i];
        atomicAdd(&g_deg_r[b.x], 1);
        atomicAdd(&g_deg_r[b.y], 1);
        atomicAdd(&g_deg_r[b.z], 1);
        atomicAdd(&g_deg_r[b.w], 1);
    }
}

// ---------------------------------------------------------------------------
__global__ void scan_part_kernel()
{
    __shared__ int sh[SCAN_B];
    const int t = threadIdx.x;
    const int idx = blockIdx.x * SCAN_B + t;
    const int v = (idx < N_NODES) ? g_deg_r[idx] : 0;
    sh[t] = v;
    __syncthreads();
#pragma unroll
    for (int o = 1; o < SCAN_B; o <<= 1) {
        int x = (t >= o) ? sh[t - o] : 0;
        __syncthreads();
        sh[t] += x;
        __syncthreads();
    }
    if (idx < N_NODES) g_off[idx] = sh[t] - v;
    if (t == SCAN_B - 1) g_bsum[blockIdx.x] = sh[t];
}

__global__ void scan_add_kernel()
{
    __shared__ int red[32];
    const int t  = threadIdx.x;
    const int sb = blockIdx.x >> 1;

    int v = (t < sb) ? g_bsum[t] : 0;
#pragma unroll
    for (int o = 16; o > 0; o >>= 1) v += __shfl_down_sync(0xffffffffu, v, o);
    if ((t & 31) == 0) red[t >> 5] = v;
    __syncthreads();
    if (t < 32) {
        int w = (t < 8) ? red[t] : 0;
#pragma unroll
        for (int o = 4; o > 0; o >>= 1) w += __shfl_down_sync(0xffffffffu, w, o);
        if (t == 0) red[0] = w;
    }
    __syncthreads();
    const int prefix = red[0];

    const int idx = blockIdx.x * 256 + t;
    if (idx < N_NODES) g_off[idx] += prefix;
}

// ---------------------------------------------------------------------------
// fill: int4-vectorized (4 edges per thread)
// ---------------------------------------------------------------------------
__global__ void fill_kernel(const int* __restrict__ s, const int* __restrict__ r)
{
    const int i = blockIdx.x * blockDim.x + threadIdx.x;
    if (i < N_EDGES / 4) {
        const int4 rr = reinterpret_cast<const int4*>(r)[i];
        const int4 ss = reinterpret_cast<const int4*>(s)[i];
        int p;
        p = atomicAdd(&g_off[rr.x], 1); g_csr[p] = ss.x;
        p = atomicAdd(&g_off[rr.y], 1); g_csr[p] = ss.y;
        p = atomicAdd(&g_off[rr.z], 1); g_csr[p] = ss.z;
        p = atomicAdd(&g_off[rr.w], 1); g_csr[p] = ss.w;
    }
}

// ---------------------------------------------------------------------------
// fp16 tensor-core GEMM (m16n8k16, fp32 accumulate), ldmatrix operand feed.
// h = (x @ W + bias) * rsqrt(max(deg_s,1)), stored fp16.
// W (128x128) loaded ONCE into smem transposed as [n][k] half2 words.
// ---------------------------------------------------------------------------
#define GBM 128
#define GBK 32
#define AS_W 20    // A row stride (words): 8-row ldmatrix phases hit all 32 banks
#define BS_W 68    // B row stride (words): 4i mod 32 distinct across 8 rows

__device__ __forceinline__ void mma_f16(float4& d,
                                        uint32_t a0, uint32_t a1, uint32_t a2, uint32_t a3,
                                        uint32_t b0, uint32_t b1)
{
    asm volatile(
        "mma.sync.aligned.m16n8k16.row.col.f32.f16.f16.f32 "
        "{%0,%1,%2,%3}, {%4,%5,%6,%7}, {%8,%9}, {%0,%1,%2,%3};"
        : "+f"(d.x), "+f"(d.y), "+f"(d.z), "+f"(d.w)
        : "r"(a0), "r"(a1), "r"(a2), "r"(a3), "r"(b0), "r"(b1));
}

__device__ __forceinline__ void ldsm_x4(uint32_t* q, uint32_t addr)
{
    asm volatile("ldmatrix.sync.aligned.m8n8.x4.shared.b16 {%0,%1,%2,%3}, [%4];"
                 : "=r"(q[0]), "=r"(q[1]), "=r"(q[2]), "=r"(q[3]) : "r"(addr));
}

__device__ __forceinline__ uint32_t cvta_smem(const void* p)
{
    uint32_t a;
    asm("{ .reg .u64 t; cvta.to.shared.u64 t, %1; cvt.u32.u64 %0, t; }"
        : "=r"(a) : "l"(p));
    return a;
}

__device__ __forceinline__ uint32_t h2bits(float lo, float hi)
{
    const __half2 h = __floats2half2_rn(lo, hi);
    return *reinterpret_cast<const uint32_t*>(&h);
}

__global__ __launch_bounds__(256, 2)
void gemm_tc_kernel(const float* __restrict__ x,
                    const float* __restrict__ w,
                    const float* __restrict__ bias)
{
    __shared__ uint32_t As[GBM][AS_W];   // 10.2 KB
    __shared__ uint32_t Bs[128][BS_W];   // 34.8 KB  (W transposed: [n][k/2])

    const int tid  = threadIdx.x;
    const int warp = tid >> 5;
    const int lane = tid & 31;
    const int gid  = lane >> 2;
    const int tig  = lane & 3;
    const int wm   = warp >> 1;
    const int wn   = warp & 1;
    const int row0 = blockIdx.x * GBM;

    // One-time: load whole W transposed into Bs[n][k/2] as half2
    {
        const int bn  = tid & 127;
        const int bk0 = (tid >> 7) * 64;
#pragma unroll
        for (int j = 0; j < 32; j++) {
            const int k = bk0 + j * 2;
            const float f0 = w[(size_t)k * D + bn];
            const float f1 = w[(size_t)(k + 1) * D + bn];
            Bs[bn][(bk0 >> 1) + j] = h2bits(f0, f1);
        }
    }

    // ldmatrix lane-address bases (byte addresses in shared space).
    // Group g = lane>>3; l7 = lane&7.
    //   A matrices per x4: m0=(rows+0,k0) m1=(rows+8,k0) m2=(rows+0,k8) m3=(rows+8,k8)
    //   B matrices per x4: m0=(n+0,k0)    m1=(n+0,k8)    m2=(n+8,k0)    m3=(n+8,k8)
    const int l7 = lane & 7;
    const int g  = lane >> 3;
    uint32_t aAddr[2], bAddr[4];
    {
        const uint32_t As_base = cvta_smem(&As[0][0]);
        const uint32_t Bs_base = cvta_smem(&Bs[0][0]);
#pragma unroll
        for (int mt = 0; mt < 2; mt++)
            aAddr[mt] = As_base +
                4u * ((wm * 32 + mt * 16 + l7 + (g & 1) * 8) * AS_W + (g >> 1) * 4);
#pragma unroll
        for (int p = 0; p < 4; p++)
            bAddr[p] = Bs_base +
                4u * ((wn * 64 + p * 16 + l7 + (g >> 1) * 8) * BS_W + (g & 1) * 4);
    }

    float4 acc[2][8];
#pragma unroll
    for (int mt = 0; mt < 2; mt++)
#pragma unroll
        for (int nt = 0; nt < 8; nt++)
            acc[mt][nt] = make_float4(0.f, 0.f, 0.f, 0.f);

    __syncthreads();

    for (int kb = 0; kb < D; kb += GBK) {
#pragma unroll
        for (int p = 0; p < 4; p++) {
            const int idx = tid + p * 256;
            const int r   = idx >> 3;
            const int c   = (idx & 7) * 4;
            const int gr  = row0 + r;
            float4 v = make_float4(0.f, 0.f, 0.f, 0.f);
            if (gr < N_NODES)
                v = *reinterpret_cast<const float4*>(&x[(size_t)gr * D + kb + c]);
            As[r][(c >> 1) + 0] = h2bits(v.x, v.y);
            As[r][(c >> 1) + 1] = h2bits(v.z, v.w);
        }
        __syncthreads();

        const int kwb = kb >> 1;   // word base into Bs rows for this K-block
#pragma unroll
        for (int kc = 0; kc < GBK; kc += 16) {
            const int kw = kc >> 1;            // 0 or 8 (word offset within tile)
            uint32_t a0[4], a1[4];
            ldsm_x4(a0, aAddr[0] + 4u * kw);
            ldsm_x4(a1, aAddr[1] + 4u * kw);
#pragma unroll
            for (int p = 0; p < 4; p++) {
                uint32_t b[4];                  // {b0(nt), b1(nt), b0(nt+1), b1(nt+1)}
                ldsm_x4(b, bAddr[p] + 4u * (kwb + kw));
                const int nt = p * 2;
                mma_f16(acc[0][nt    ], a0[0], a0[1], a0[2], a0[3], b[0], b[1]);
                mma_f16(acc[0][nt + 1], a0[0], a0[1], a0[2], a0[3], b[2], b[3]);
                mma_f16(acc[1][nt    ], a1[0], a1[1], a1[2], a1[3], b[0], b[1]);
                mma_f16(acc[1][nt + 1], a1[0], a1[1], a1[2], a1[3], b[2], b[3]);
            }
        }
        __syncthreads();
    }

    // Epilogue: bias + rsqrt(deg_s), convert to fp16, store half2.
    float2 bv[8];
#pragma unroll
    for (int nt = 0; nt < 8; nt++) {
        const int n = wn * 64 + nt * 8 + tig * 2;
        bv[nt].x = __ldg(&bias[n]);
        bv[nt].y = __ldg(&bias[n + 1]);
    }
#pragma unroll
    for (int mt = 0; mt < 2; mt++) {
        const int rbase = row0 + wm * 32 + mt * 16;
        const int r0 = rbase + gid;
        const int r1 = rbase + gid + 8;
        const float s0 = (r0 < N_NODES) ? rsqrtf(fmaxf((float)g_deg_s[r0], 1.0f)) : 0.f;
        const float s1 = (r1 < N_NODES) ? rsqrtf(fmaxf((float)g_deg_s[r1], 1.0f)) : 0.f;
#pragma unroll
        for (int nt = 0; nt < 8; nt++) {
            const int n = wn * 64 + nt * 8 + tig * 2;
            if (r0 < N_NODES) {
                const __half2 o = __floats2half2_rn((acc[mt][nt].x + bv[nt].x) * s0,
                                                    (acc[mt][nt].y + bv[nt].y) * s0);
                *reinterpret_cast<__half2*>(&g_h[(size_t)r0 * D + n]) = o;
            }
            if (r1 < N_NODES) {
                const __half2 o = __floats2half2_rn((acc[mt][nt].z + bv[nt].x) * s1,
                                                    (acc[mt][nt].w + bv[nt].y) * s1);
                *reinterpret_cast<__half2*>(&g_h[(size_t)r1 * D + n]) = o;
            }
        }
    }
}

// ---------------------------------------------------------------------------
// Gather-aggregate over fp16 h, fp32 accumulation. One warp per node.
// Tail: re-zero g_deg_s/g_deg_r for the next call.
// ---------------------------------------------------------------------------
__device__ __forceinline__ void acc_row(float4& acc, const uint2 raw)
{
    const __half2 h0 = *reinterpret_cast<const __half2*>(&raw.x);
    const __half2 h1 = *reinterpret_cast<const __half2*>(&raw.y);
    const float2 f0 = __half22float2(h0);
    const float2 f1 = __half22float2(h1);
    acc.x += f0.x; acc.y += f0.y; acc.z += f1.x; acc.w += f1.y;
}

__global__ __launch_bounds__(256)
void gather_kernel(float* __restrict__ out)
{
    const int node = (blockIdx.x * blockDim.x + threadIdx.x) >> 5;
    const int lane = threadIdx.x & 31;
    if (node >= N_NODES) return;

    const int deg = g_deg_r[node];
    const int end = g_off[node];        // after fill, g_off holds row END
    const int beg = end - deg;

    if (lane == 0) g_deg_r[node] = 0;
    if (lane == 1) g_deg_s[node] = 0;

    float4 acc = make_float4(0.f, 0.f, 0.f, 0.f);
    const int fo = lane * 4;

    int j = beg;
    for (; j + 4 <= end; j += 4) {
        const int s0 = g_csr[j + 0];
        const int s1 = g_csr[j + 1];
        const int s2 = g_csr[j + 2];
        const int s3 = g_csr[j + 3];
        const uint2 v0 = *reinterpret_cast<const uint2*>(&g_h[(size_t)s0 * D + fo]);
        const uint2 v1 = *reinterpret_cast<const uint2*>(&g_h[(size_t)s1 * D + fo]);
        const uint2 v2 = *reinterpret_cast<const uint2*>(&g_h[(size_t)s2 * D + fo]);
        const uint2 v3 = *reinterpret_cast<const uint2*>(&g_h[(size_t)s3 * D + fo]);
        acc_row(acc, v0);
        acc_row(acc, v1);
        acc_row(acc, v2);
        acc_row(acc, v3);
    }
    for (; j < end; j++) {
        const int ss = g_csr[j];
        const uint2 v = *reinterpret_cast<const uint2*>(&g_h[(size_t)ss * D + fo]);
        acc_row(acc, v);
    }

    const float sc = rsqrtf(fmaxf((float)deg, 1.0f));
    acc.x *= sc; acc.y *= sc; acc.z *= sc; acc.w *= sc;
    *reinterpret_cast<float4*>(&out[(size_t)node * D + fo]) = acc;
}

// ---------------------------------------------------------------------------
// Topology: degree -> fork GEMM (side) parallel to scan -> fill (main);
// join before gather.
// ---------------------------------------------------------------------------
extern "C" void kernel_launch(void* const* d_in, const int* in_sizes, int n_in,
                              void* d_out, int out_size)
{
    const float* x       = (const float*)d_in[0];
    const int*   senders = (const int*)d_in[1];
    const int*   recvs   = (const int*)d_in[2];
    const float* weight  = (const float*)d_in[4];
    const float* bias    = (const float*)d_in[5];
    float* out = (float*)d_out;

    static cudaStream_t side = nullptr;
    static cudaEvent_t  evA  = nullptr;
    static cudaEvent_t  evB  = nullptr;
    if (side == nullptr) {
        cudaStreamCreateWithFlags(&side, cudaStreamNonBlocking);
        cudaEventCreateWithFlags(&evA, cudaEventDisableTiming);
        cudaEventCreateWithFlags(&evB, cudaEventDisableTiming);
    }

    degree_kernel<<<(N_EDGES / 4 + 255) / 256, 256>>>(senders, recvs);

    cudaEventRecord(evA, 0);
    cudaStreamWaitEvent(side, evA, 0);
    gemm_tc_kernel<<<(N_NODES + GBM - 1) / GBM, 256, 0, side>>>(x, weight, bias);
    cudaEventRecord(evB, side);

    scan_part_kernel<<<NUM_SCAN_BLOCKS, SCAN_B>>>();
    scan_add_kernel<<<(N_NODES + 255) / 256, 256>>>();
    fill_kernel<<<(N_EDGES / 4 + 255) / 256, 256>>>(senders, recvs);

    cudaStreamWaitEvent(0, evB, 0);
    gather_kernel<<<(N_NODES * 32 + 255) / 256, 256>>>(out);
}